// round 5
// baseline (speedup 1.0000x reference)
#include <cuda_runtime.h>
#include <stdint.h>

#define BB 2
#define SS 2048
#define DD 1024
#define HH 16
#define NR (BB*SS)            // 4096 rows
#define ATT_SCALE 0.125f      // 1/sqrt(64)

// ---------------- device scratch (no cudaMalloc allowed) ----------------
static __device__ float g_W3[3 * DD * DD];          // concat(Wq,Wk,Wv), tf32-rounded
static __device__ float g_Wo[DD * DD];              // Wo, tf32-rounded
static __device__ float g_b3[3 * DD];
static __device__ float g_X[(size_t)NR * DD];       // x, tf32-rounded
static __device__ float g_QKV[(size_t)NR * 3 * DD]; // (4096, 3072): Q|K|V (tf32-clean)
static __device__ float g_C[(size_t)NR * DD];       // ctx (B,S,D)   (tf32-clean)
static __device__ float g_m[(size_t)32 * SS * 16];  // per-tile row max
static __device__ float g_l[(size_t)32 * SS * 16];  // per-tile row sumexp
static __device__ float g_M[(size_t)32 * SS];       // final row max
static __device__ float g_IL[(size_t)32 * SS];      // final 1/rowsum

// ---------------- tf32 / mma / cp.async helpers ----------------
__device__ __forceinline__ uint32_t f2t(float x) {
    uint32_t r;
    asm("cvt.rna.tf32.f32 %0, %1;" : "=r"(r) : "f"(x));
    return r;
}
__device__ __forceinline__ float f2tf(float x) { return __uint_as_float(f2t(x)); }

__device__ __forceinline__ void mma8(float* c, const uint32_t* a, const uint32_t* b) {
    asm volatile(
        "mma.sync.aligned.m16n8k8.row.col.f32.tf32.tf32.f32 "
        "{%0,%1,%2,%3},{%4,%5,%6,%7},{%8,%9},{%0,%1,%2,%3};"
        : "+f"(c[0]), "+f"(c[1]), "+f"(c[2]), "+f"(c[3])
        : "r"(a[0]), "r"(a[1]), "r"(a[2]), "r"(a[3]), "r"(b[0]), "r"(b[1]));
}
__device__ __forceinline__ void cp16(float* dst, const float* src) {
    uint32_t d = (uint32_t)__cvta_generic_to_shared(dst);
    asm volatile("cp.async.cg.shared.global [%0], [%1], 16;" :: "r"(d), "l"(src));
}
__device__ __forceinline__ void cp_commit() { asm volatile("cp.async.commit_group;"); }
template <int N>
__device__ __forceinline__ void cp_wait() { asm volatile("cp.async.wait_group %0;" :: "n"(N)); }

// ---------------- prep: concat + round weights; round x ----------------
__global__ void concat_kernel(const float* __restrict__ Wq, const float* __restrict__ Wk,
                              const float* __restrict__ Wv, const float* __restrict__ Wo,
                              const float* __restrict__ bq, const float* __restrict__ bk,
                              const float* __restrict__ bv) {
    int i = blockIdx.x * 256 + threadIdx.x;
    if (i < DD * DD) {
        g_W3[i]               = f2tf(Wq[i]);
        g_W3[DD * DD + i]     = f2tf(Wk[i]);
        g_W3[2 * DD * DD + i] = f2tf(Wv[i]);
        g_Wo[i]               = f2tf(Wo[i]);
    }
    if (i < DD) {
        g_b3[i]          = bq[i];
        g_b3[DD + i]     = bk[i];
        g_b3[2 * DD + i] = bv[i];
    }
}
__global__ void roundx_kernel(const float* __restrict__ x) {
    size_t i = (size_t)blockIdx.x * 256 + threadIdx.x;
    g_X[i] = f2tf(x[i]);
}

// ---------------- NT GEMM (tf32 tensor, cp.async 4-stage) ----------------
#define GSTG 2560   // 128*20 floats per stage per operand
template <bool RND>
__global__ __launch_bounds__(256, 2) void gemm_v3(
    const float* __restrict__ A, const float* __restrict__ Bw,
    const float* __restrict__ bias, float* __restrict__ C,
    int M, int N, int K)
{
    extern __shared__ float sm[];
    float* As = sm;               // [4][128][20]
    float* Bs = sm + 4 * GSTG;    // [4][128][20]

    const int t = threadIdx.x, lane = t & 31, w = t >> 5;
    const int g = lane >> 2, tg = lane & 3;
    const int wm = w & 3, wn = w >> 2;
    const int row0 = blockIdx.y * 128, col0 = blockIdx.x * 128;

    const int lrow = t >> 1, lseg = (t & 1) * 8;
    const float* Ap = A  + (size_t)(row0 + lrow) * K + lseg;
    const float* Bp = Bw + (size_t)(col0 + lrow) * K + lseg;
    float* Asd = As + lrow * 20 + lseg;
    float* Bsd = Bs + lrow * 20 + lseg;

    float acc[2][8][4];
#pragma unroll
    for (int i = 0; i < 2; i++)
#pragma unroll
        for (int j = 0; j < 8; j++)
#pragma unroll
            for (int q = 0; q < 4; q++) acc[i][j][q] = 0.f;

    const int nk = K / 16;
#pragma unroll
    for (int s = 0; s < 3; s++) {
        cp16(Asd + s * GSTG, Ap + s * 16);
        cp16(Asd + s * GSTG + 4, Ap + s * 16 + 4);
        cp16(Bsd + s * GSTG, Bp + s * 16);
        cp16(Bsd + s * GSTG + 4, Bp + s * 16 + 4);
        cp_commit();
    }

    for (int kc = 0; kc < nk; kc++) {
        cp_wait<2>();
        __syncthreads();
        if (kc + 3 < nk) {
            const int s = (kc + 3) & 3;
            const int k0 = (kc + 3) * 16;
            cp16(Asd + s * GSTG, Ap + k0);
            cp16(Asd + s * GSTG + 4, Ap + k0 + 4);
            cp16(Bsd + s * GSTG, Bp + k0);
            cp16(Bsd + s * GSTG + 4, Bp + k0 + 4);
        }
        cp_commit();

        const float* a = As + (kc & 3) * GSTG;
        const float* b = Bs + (kc & 3) * GSTG;
#pragma unroll
        for (int ks = 0; ks < 16; ks += 8) {
            uint32_t af[2][4], bf[8][2];
#pragma unroll
            for (int mt = 0; mt < 2; mt++) {
                const int r = wm * 32 + mt * 16 + g;
                af[mt][0] = __float_as_uint(a[r * 20 + ks + tg]);
                af[mt][1] = __float_as_uint(a[(r + 8) * 20 + ks + tg]);
                af[mt][2] = __float_as_uint(a[r * 20 + ks + tg + 4]);
                af[mt][3] = __float_as_uint(a[(r + 8) * 20 + ks + tg + 4]);
            }
#pragma unroll
            for (int nt = 0; nt < 8; nt++) {
                const int n = wn * 64 + nt * 8 + g;
                bf[nt][0] = __float_as_uint(b[n * 20 + ks + tg]);
                bf[nt][1] = __float_as_uint(b[n * 20 + ks + tg + 4]);
            }
#pragma unroll
            for (int mt = 0; mt < 2; mt++)
#pragma unroll
                for (int nt = 0; nt < 8; nt++)
                    mma8(acc[mt][nt], af[mt], bf[nt]);
        }
    }

#pragma unroll
    for (int mt = 0; mt < 2; mt++) {
        const int r = row0 + wm * 32 + mt * 16 + g;
#pragma unroll
        for (int nt = 0; nt < 8; nt++) {
            const int cc = col0 + wn * 64 + nt * 8 + 2 * tg;
            float2 v0, v1;
            v0.x = acc[mt][nt][0] + bias[cc];
            v0.y = acc[mt][nt][1] + bias[cc + 1];
            v1.x = acc[mt][nt][2] + bias[cc];
            v1.y = acc[mt][nt][3] + bias[cc + 1];
            if (RND) {
                v0.x = f2tf(v0.x); v0.y = f2tf(v0.y);
                v1.x = f2tf(v1.x); v1.y = f2tf(v1.y);
            }
            *(float2*)(C + (size_t)r * N + cc)       = v0;
            *(float2*)(C + (size_t)(r + 8) * N + cc) = v1;
        }
    }
}

// ---------------- scores v4: block per (z, 128-row q band) ----------------
// Stationary Q tile; stream K tiles with 2-stage cp.async; emit raw scores
// (scaled) + per-tile row stats (max, sumexp) for the later softmax fold.
#define QTILE (128*68)
__global__ __launch_bounds__(256) void scores_v4(
    const float* __restrict__ QKV, float* __restrict__ attn,
    float* __restrict__ gm, float* __restrict__ gl)
{
    extern __shared__ float sm[];
    float* Qs  = sm;                      // [128][68]
    float* Ks  = sm + QTILE;              // [2][128][68]
    float* red = sm + 3 * QTILE;          // red_m[2][128], red_l[2][128]
    float* red_m = red;
    float* red_l = red + 256;

    const int qt = 15 - (int)blockIdx.x;  // longest first
    const int z = blockIdx.y;
    const int b = z >> 4, h = z & 15;
    const int t = threadIdx.x, lane = t & 31, w = t >> 5;
    const int g = lane >> 2, tg = lane & 3;
    const int wm = w & 3, wn = w >> 2;

    const int lrow = t >> 1, lseg = (t & 1) * 32;
    const float* Qp = QKV + ((size_t)(b * SS) + qt * 128 + lrow) * 3072 + h * 64 + lseg;
    const float* Kp = QKV + ((size_t)(b * SS) + lrow) * 3072 + DD + h * 64 + lseg;
    float* Qsd = Qs + lrow * 68 + lseg;
    float* Ksd = Ks + lrow * 68 + lseg;

    // prologue: Q + K tile 0
#pragma unroll
    for (int j = 0; j < 8; j++) {
        cp16(Qsd + j * 4, Qp + j * 4);
        cp16(Ksd + j * 4, Kp + j * 4);
    }
    cp_commit();

    const int nkt = qt + 1;
    for (int kt = 0; kt < nkt; kt++) {
        if (kt + 1 < nkt) {
            const int st = (kt + 1) & 1;
#pragma unroll
            for (int j = 0; j < 8; j++)
                cp16(Ksd + st * QTILE + j * 4, Kp + (size_t)(kt + 1) * 128 * 3072 + j * 4);
        }
        cp_commit();
        cp_wait<1>();
        __syncthreads();

        const float* kk = Ks + (kt & 1) * QTILE;
        float acc[2][8][4];
#pragma unroll
        for (int i = 0; i < 2; i++)
#pragma unroll
            for (int j = 0; j < 8; j++)
#pragma unroll
                for (int q = 0; q < 4; q++) acc[i][j][q] = 0.f;

#pragma unroll
        for (int ks = 0; ks < 64; ks += 8) {
            uint32_t af[2][4], bf[8][2];
#pragma unroll
            for (int mt = 0; mt < 2; mt++) {
                const int r = wm * 32 + mt * 16 + g;
                af[mt][0] = __float_as_uint(Qs[r * 68 + ks + tg]);
                af[mt][1] = __float_as_uint(Qs[(r + 8) * 68 + ks + tg]);
                af[mt][2] = __float_as_uint(Qs[r * 68 + ks + tg + 4]);
                af[mt][3] = __float_as_uint(Qs[(r + 8) * 68 + ks + tg + 4]);
            }
#pragma unroll
            for (int nt = 0; nt < 8; nt++) {
                const int n = wn * 64 + nt * 8 + g;
                bf[nt][0] = __float_as_uint(kk[n * 68 + ks + tg]);
                bf[nt][1] = __float_as_uint(kk[n * 68 + ks + tg + 4]);
            }
#pragma unroll
            for (int mt = 0; mt < 2; mt++)
#pragma unroll
                for (int nt = 0; nt < 8; nt++)
                    mma8(acc[mt][nt], af[mt], bf[nt]);
        }

        // scale, store raw scores, compute per-tile row stats
#pragma unroll
        for (int mt = 0; mt < 2; mt++) {
            const int rg0 = qt * 128 + wm * 32 + mt * 16 + g;  // global row A
            const int rg1 = rg0 + 8;                           // global row B
            float mA = -1e30f, mB = -1e30f;
#pragma unroll
            for (int nt = 0; nt < 8; nt++) {
#pragma unroll
                for (int q = 0; q < 4; q++) acc[mt][nt][q] *= ATT_SCALE;
                const int c0 = kt * 128 + wn * 64 + nt * 8 + 2 * tg;
                float2 v0, v1;
                v0.x = acc[mt][nt][0]; v0.y = acc[mt][nt][1];
                v1.x = acc[mt][nt][2]; v1.y = acc[mt][nt][3];
                *(float2*)(attn + ((size_t)z * SS + rg0) * SS + c0) = v0;
                *(float2*)(attn + ((size_t)z * SS + rg1) * SS + c0) = v1;
                if (c0     <= rg0) mA = fmaxf(mA, acc[mt][nt][0]);
                if (c0 + 1 <= rg0) mA = fmaxf(mA, acc[mt][nt][1]);
                if (c0     <= rg1) mB = fmaxf(mB, acc[mt][nt][2]);
                if (c0 + 1 <= rg1) mB = fmaxf(mB, acc[mt][nt][3]);
            }
            mA = fmaxf(mA, __shfl_xor_sync(~0u, mA, 1));
            mA = fmaxf(mA, __shfl_xor_sync(~0u, mA, 2));
            mB = fmaxf(mB, __shfl_xor_sync(~0u, mB, 1));
            mB = fmaxf(mB, __shfl_xor_sync(~0u, mB, 2));
            float lA = 0.f, lB = 0.f;
#pragma unroll
            for (int nt = 0; nt < 8; nt++) {
                const int c0 = kt * 128 + wn * 64 + nt * 8 + 2 * tg;
                if (c0     <= rg0) lA += __expf(acc[mt][nt][0] - mA);
                if (c0 + 1 <= rg0) lA += __expf(acc[mt][nt][1] - mA);
                if (c0     <= rg1) lB += __expf(acc[mt][nt][2] - mB);
                if (c0 + 1 <= rg1) lB += __expf(acc[mt][nt][3] - mB);
            }
            lA += __shfl_xor_sync(~0u, lA, 1); lA += __shfl_xor_sync(~0u, lA, 2);
            lB += __shfl_xor_sync(~0u, lB, 1); lB += __shfl_xor_sync(~0u, lB, 2);
            if (tg == 0) {
                const int rl = wm * 32 + mt * 16 + g;
                red_m[wn * 128 + rl]     = mA;  red_l[wn * 128 + rl]     = lA;
                red_m[wn * 128 + rl + 8] = mB;  red_l[wn * 128 + rl + 8] = lB;
            }
        }
        __syncthreads();
        if (t < 128) {
            float ma = red_m[t], mb = red_m[128 + t];
            float la = red_l[t], lb = red_l[128 + t];
            float Mt = fmaxf(ma, mb);
            float Lt = ((ma > -1e29f) ? la * __expf(ma - Mt) : 0.f)
                     + ((mb > -1e29f) ? lb * __expf(mb - Mt) : 0.f);
            const size_t sidx = ((size_t)z * SS + qt * 128 + t) * 16 + kt;
            gm[sidx] = Mt;
            gl[sidx] = Lt;
        }
    }
}

// ---------------- reduce per-row stats: (M, 1/L) ----------------
__global__ void reduce_stats(const float* __restrict__ gm, const float* __restrict__ gl,
                             float* __restrict__ gM, float* __restrict__ gIL)
{
    const int row = blockIdx.x * 256 + threadIdx.x;     // 0..65535
    const int q = row & (SS - 1);
    const int nt_ = (q >> 7) + 1;
    const float* mrow = gm + (size_t)row * 16;
    const float* lrow = gl + (size_t)row * 16;
    float M = -1e30f;
    for (int k = 0; k < nt_; k++) M = fmaxf(M, mrow[k]);
    float L = 0.f;
    for (int k = 0; k < nt_; k++) L += lrow[k] * __expf(mrow[k] - M);
    gM[row]  = M;
    gIL[row] = 1.0f / L;
}

// ---------------- ctx v4: normalize + write attn + attn@V, fused ----------
#define PSTG (128*68)
#define VSTG (64*72)
__global__ __launch_bounds__(256) void ctx_v4(
    float* __restrict__ attn, const float* __restrict__ QKV,
    const float* __restrict__ gM, const float* __restrict__ gIL,
    float* __restrict__ Cout)
{
    extern __shared__ float sm[];
    float* Ps  = sm;                       // [2][128][68]
    float* Vs  = sm + 2 * PSTG;            // [2][64][72]
    float* sM  = sm + 2 * PSTG + 2 * VSTG; // [128]
    float* sIL = sM + 128;                 // [128]

    const int qt = 15 - (int)blockIdx.x;   // longest first
    const int z = blockIdx.y;
    const int b = z >> 4, h = z & 15;
    const int t = threadIdx.x, lane = t & 31, w = t >> 5;
    const int g = lane >> 2, tg = lane & 3;
    const int wm = w & 3, wn = w >> 2;

    const int prow = t >> 1, pseg = (t & 1) * 32;
    const int vrow = t >> 2, vseg = (t & 3) * 16;
    float* Pp = attn + ((size_t)z * SS + qt * 128 + prow) * SS + pseg;
    const float* Vp = QKV + ((size_t)(b * SS) + vrow) * 3072 + 2 * DD + h * 64 + vseg;
    float* Psd = Ps + prow * 68 + pseg;
    float* Vsd = Vs + vrow * 72 + vseg;

    if (t < 128) {
        sM[t]  = gM[(size_t)z * SS + qt * 128 + t];
        sIL[t] = gIL[(size_t)z * SS + qt * 128 + t];
    }

    const int cnt = 2 * qt + 2;

    float acc[2][4][4];
#pragma unroll
    for (int i = 0; i < 2; i++)
#pragma unroll
        for (int j = 0; j < 4; j++)
#pragma unroll
            for (int q = 0; q < 4; q++) acc[i][j][q] = 0.f;

    // prologue: stage 0
#pragma unroll
    for (int j = 0; j < 8; j++) cp16(Psd + j * 4, Pp + j * 4);
#pragma unroll
    for (int j = 0; j < 4; j++) cp16(Vsd + j * 4, Vp + j * 4);
    cp_commit();

    for (int kti = 0; kti < cnt; kti++) {
        if (kti + 1 < cnt) {
            const int st = (kti + 1) & 1;
#pragma unroll
            for (int j = 0; j < 8; j++)
                cp16(Psd + st * PSTG + j * 4, Pp + (kti + 1) * 64 + j * 4);
#pragma unroll
            for (int j = 0; j < 4; j++)
                cp16(Vsd + st * VSTG + j * 4, Vp + (size_t)(kti + 1) * 64 * 3072 + j * 4);
        }
        cp_commit();
        cp_wait<1>();
        __syncthreads();

        // normalize current P tile in smem + write probabilities to gmem
        {
            const float Mr = sM[prow], iL = sIL[prow];
            const int rowg = qt * 128 + prow;
            float* psd = Ps + (kti & 1) * PSTG + prow * 68 + pseg;
#pragma unroll
            for (int j = 0; j < 8; j++) {
                float4 v = *(float4*)(psd + j * 4);
                const int c = kti * 64 + pseg + j * 4;
                v.x = (c     <= rowg) ? __expf(v.x - Mr) * iL : 0.f;
                v.y = (c + 1 <= rowg) ? __expf(v.y - Mr) * iL : 0.f;
                v.z = (c + 2 <= rowg) ? __expf(v.z - Mr) * iL : 0.f;
                v.w = (c + 3 <= rowg) ? __expf(v.w - Mr) * iL : 0.f;
                *(float4*)(psd + j * 4) = v;
                *(float4*)(Pp + kti * 64 + j * 4) = v;
            }
        }
        __syncthreads();

        const float* pp = Ps + (kti & 1) * PSTG;
        const float* vv = Vs + (kti & 1) * VSTG;
#pragma unroll
        for (int ks = 0; ks < 64; ks += 8) {
            uint32_t af[2][4], bf[4][2];
#pragma unroll
            for (int mt = 0; mt < 2; mt++) {
                const int r = wm * 32 + mt * 16 + g;
                af[mt][0] = f2t(pp[r * 68 + ks + tg]);
                af[mt][1] = f2t(pp[(r + 8) * 68 + ks + tg]);
                af[mt][2] = f2t(pp[r * 68 + ks + tg + 4]);
                af[mt][3] = f2t(pp[(r + 8) * 68 + ks + tg + 4]);
            }
#pragma unroll
            for (int nt = 0; nt < 4; nt++) {
                const int n = wn * 32 + nt * 8 + g;
                bf[nt][0] = __float_as_uint(vv[(ks + tg) * 72 + n]);
                bf[nt][1] = __float_as_uint(vv[(ks + tg + 4) * 72 + n]);
            }
#pragma unroll
            for (int mt = 0; mt < 2; mt++)
#pragma unroll
                for (int nt = 0; nt < 4; nt++)
                    mma8(acc[mt][nt], af[mt], bf[nt]);
        }
        __syncthreads();
    }

    // zero-fill the strict upper triangle region of these rows
    {
        const float4 z4 = make_float4(0.f, 0.f, 0.f, 0.f);
        for (int c = cnt * 64; c < SS; c += 64) {
#pragma unroll
            for (int j = 0; j < 8; j++)
                *(float4*)(Pp + c + j * 4) = z4;
        }
    }

#pragma unroll
    for (int mt = 0; mt < 2; mt++) {
        const int qrow = qt * 128 + wm * 32 + mt * 16 + g;
#pragma unroll
        for (int nt = 0; nt < 4; nt++) {
            const int cc = h * 64 + wn * 32 + nt * 8 + 2 * tg;
            float2 v0, v1;
            v0.x = f2tf(acc[mt][nt][0]); v0.y = f2tf(acc[mt][nt][1]);
            v1.x = f2tf(acc[mt][nt][2]); v1.y = f2tf(acc[mt][nt][3]);
            *(float2*)(Cout + ((size_t)(b * SS) + qrow) * DD + cc)     = v0;
            *(float2*)(Cout + ((size_t)(b * SS) + qrow + 8) * DD + cc) = v1;
        }
    }
}

// ---------------- launch ----------------
extern "C" void kernel_launch(void* const* d_in, const int* in_sizes, int n_in,
                              void* d_out, int out_size)
{
    const float* x  = (const float*)d_in[0];
    const float* Wq = (const float*)d_in[1];
    const float* bq = (const float*)d_in[2];
    const float* Wk = (const float*)d_in[3];
    const float* bk = (const float*)d_in[4];
    const float* Wv = (const float*)d_in[5];
    const float* bv = (const float*)d_in[6];
    const float* Wo = (const float*)d_in[7];
    const float* bo = (const float*)d_in[8];

    float* out  = (float*)d_out;
    float* attn = out + (size_t)NR * DD;   // tuple order: (out, attn)

    float *pW3, *pWo, *pb3, *pX, *pQKV, *pC, *pm, *pl, *pM, *pIL;
    cudaGetSymbolAddress((void**)&pW3,  g_W3);
    cudaGetSymbolAddress((void**)&pWo,  g_Wo);
    cudaGetSymbolAddress((void**)&pb3,  g_b3);
    cudaGetSymbolAddress((void**)&pX,   g_X);
    cudaGetSymbolAddress((void**)&pQKV, g_QKV);
    cudaGetSymbolAddress((void**)&pC,   g_C);
    cudaGetSymbolAddress((void**)&pm,   g_m);
    cudaGetSymbolAddress((void**)&pl,   g_l);
    cudaGetSymbolAddress((void**)&pM,   g_M);
    cudaGetSymbolAddress((void**)&pIL,  g_IL);

    const int gemm_smem   = 4 * GSTG * 2 * 4;                      // 81920
    const int scores_smem = (3 * QTILE + 512) * 4;                 // 106496
    const int ctx_smem    = (2 * PSTG + 2 * VSTG + 256) * 4;       // 107520
    cudaFuncSetAttribute(gemm_v3<true>,  cudaFuncAttributeMaxDynamicSharedMemorySize, gemm_smem);
    cudaFuncSetAttribute(gemm_v3<false>, cudaFuncAttributeMaxDynamicSharedMemorySize, gemm_smem);
    cudaFuncSetAttribute(scores_v4,      cudaFuncAttributeMaxDynamicSharedMemorySize, scores_smem);
    cudaFuncSetAttribute(ctx_v4,         cudaFuncAttributeMaxDynamicSharedMemorySize, ctx_smem);

    // 1) prep
    concat_kernel<<<(DD * DD + 255) / 256, 256>>>(Wq, Wk, Wv, Wo, bq, bk, bv);
    roundx_kernel<<<(NR * DD) / 256, 256>>>(x);

    // 2) fused QKV projection (stores tf32-rounded outputs)
    gemm_v3<true><<<dim3(3072 / 128, NR / 128), 256, gemm_smem>>>(pX, pW3, pb3, pQKV, NR, 3072, DD);

    // 3) streamed causal scores + per-tile stats
    scores_v4<<<dim3(SS / 128, BB * HH), 256, scores_smem>>>(pQKV, attn, pm, pl);

    // 4) fold stats -> per-row (M, 1/L)
    reduce_stats<<<(32 * SS) / 256, 256>>>(pm, pl, pM, pIL);

    // 5) fused normalize + attn write + ctx = attn @ V
    ctx_v4<<<dim3(SS / 128, BB * HH), 256, ctx_smem>>>(attn, pQKV, pM, pIL, pC);

    // 6) output projection (exact fp32 epilogue)
    gemm_v3<false><<<dim3(DD / 128, NR / 128), 256, gemm_smem>>>(pC, pWo, bo, out, NR, DD, DD);
}

// round 6
// speedup vs baseline: 1.2724x; 1.2724x over previous
#include <cuda_runtime.h>
#include <stdint.h>

#define BB 2
#define SS 2048
#define DD 1024
#define HH 16
#define NR (BB*SS)            // 4096 rows
#define ATT_SCALE 0.125f      // 1/sqrt(64)

// ---------------- device scratch (no cudaMalloc allowed) ----------------
static __device__ float g_W3[3 * DD * DD];          // concat(Wq,Wk,Wv), tf32-rounded
static __device__ float g_Wo[DD * DD];              // Wo, tf32-rounded
static __device__ float g_b3[3 * DD];
static __device__ float g_X[(size_t)NR * DD];       // x, tf32-rounded
static __device__ float g_QKV[(size_t)NR * 3 * DD]; // (4096, 3072): Q|K|V (tf32-clean)
static __device__ float g_C[(size_t)NR * DD];       // ctx (B,S,D)   (tf32-clean)

// ---------------- tf32 / mma / cp.async helpers ----------------
__device__ __forceinline__ uint32_t f2t(float x) {
    uint32_t r;
    asm("cvt.rna.tf32.f32 %0, %1;" : "=r"(r) : "f"(x));
    return r;
}
__device__ __forceinline__ float f2tf(float x) { return __uint_as_float(f2t(x)); }

__device__ __forceinline__ void mma8(float* c, const uint32_t* a, const uint32_t* b) {
    asm volatile(
        "mma.sync.aligned.m16n8k8.row.col.f32.tf32.tf32.f32 "
        "{%0,%1,%2,%3},{%4,%5,%6,%7},{%8,%9},{%0,%1,%2,%3};"
        : "+f"(c[0]), "+f"(c[1]), "+f"(c[2]), "+f"(c[3])
        : "r"(a[0]), "r"(a[1]), "r"(a[2]), "r"(a[3]), "r"(b[0]), "r"(b[1]));
}
__device__ __forceinline__ void cp16(float* dst, const float* src) {
    uint32_t d = (uint32_t)__cvta_generic_to_shared(dst);
    asm volatile("cp.async.cg.shared.global [%0], [%1], 16;" :: "r"(d), "l"(src));
}
__device__ __forceinline__ void cp_commit() { asm volatile("cp.async.commit_group;"); }
template <int N>
__device__ __forceinline__ void cp_wait() { asm volatile("cp.async.wait_group %0;" :: "n"(N)); }

// ---------------- prep: concat + round weights; round x (float4) ----------------
__global__ void concat_kernel(const float4* __restrict__ Wq, const float4* __restrict__ Wk,
                              const float4* __restrict__ Wv, const float4* __restrict__ Wo,
                              const float* __restrict__ bq, const float* __restrict__ bk,
                              const float* __restrict__ bv) {
    const int i = blockIdx.x * 256 + threadIdx.x;      // float4 index, < DD*DD/4
    float4* w3 = (float4*)g_W3;
    float4* wo = (float4*)g_Wo;
    const int q4 = DD * DD / 4;
    float4 a = Wq[i], b = Wk[i], c = Wv[i], d = Wo[i];
    a.x = f2tf(a.x); a.y = f2tf(a.y); a.z = f2tf(a.z); a.w = f2tf(a.w);
    b.x = f2tf(b.x); b.y = f2tf(b.y); b.z = f2tf(b.z); b.w = f2tf(b.w);
    c.x = f2tf(c.x); c.y = f2tf(c.y); c.z = f2tf(c.z); c.w = f2tf(c.w);
    d.x = f2tf(d.x); d.y = f2tf(d.y); d.z = f2tf(d.z); d.w = f2tf(d.w);
    w3[i] = a; w3[q4 + i] = b; w3[2 * q4 + i] = c; wo[i] = d;
    if (i < DD) {
        g_b3[i]          = bq[i];
        g_b3[DD + i]     = bk[i];
        g_b3[2 * DD + i] = bv[i];
    }
}
__global__ void roundx_kernel(const float4* __restrict__ x) {
    const size_t i = (size_t)blockIdx.x * 256 + threadIdx.x;
    float4 v = x[i];
    v.x = f2tf(v.x); v.y = f2tf(v.y); v.z = f2tf(v.z); v.w = f2tf(v.w);
    ((float4*)g_X)[i] = v;
}

// ---------------- NT GEMM (tf32 tensor, cp.async 4-stage) ----------------
#define GSTG 2560   // 128*20 floats per stage per operand
template <bool RND>
__global__ __launch_bounds__(256, 2) void gemm_v3(
    const float* __restrict__ A, const float* __restrict__ Bw,
    const float* __restrict__ bias, float* __restrict__ C,
    int M, int N, int K)
{
    extern __shared__ float sm[];
    float* As = sm;               // [4][128][20]
    float* Bs = sm + 4 * GSTG;    // [4][128][20]

    const int t = threadIdx.x, lane = t & 31, w = t >> 5;
    const int g = lane >> 2, tg = lane & 3;
    const int wm = w & 3, wn = w >> 2;
    const int row0 = blockIdx.y * 128, col0 = blockIdx.x * 128;

    const int lrow = t >> 1, lseg = (t & 1) * 8;
    const float* Ap = A  + (size_t)(row0 + lrow) * K + lseg;
    const float* Bp = Bw + (size_t)(col0 + lrow) * K + lseg;
    float* Asd = As + lrow * 20 + lseg;
    float* Bsd = Bs + lrow * 20 + lseg;

    float acc[2][8][4];
#pragma unroll
    for (int i = 0; i < 2; i++)
#pragma unroll
        for (int j = 0; j < 8; j++)
#pragma unroll
            for (int q = 0; q < 4; q++) acc[i][j][q] = 0.f;

    const int nk = K / 16;
#pragma unroll
    for (int s = 0; s < 3; s++) {
        cp16(Asd + s * GSTG, Ap + s * 16);
        cp16(Asd + s * GSTG + 4, Ap + s * 16 + 4);
        cp16(Bsd + s * GSTG, Bp + s * 16);
        cp16(Bsd + s * GSTG + 4, Bp + s * 16 + 4);
        cp_commit();
    }

    for (int kc = 0; kc < nk; kc++) {
        cp_wait<2>();
        __syncthreads();
        if (kc + 3 < nk) {
            const int s = (kc + 3) & 3;
            const int k0 = (kc + 3) * 16;
            cp16(Asd + s * GSTG, Ap + k0);
            cp16(Asd + s * GSTG + 4, Ap + k0 + 4);
            cp16(Bsd + s * GSTG, Bp + k0);
            cp16(Bsd + s * GSTG + 4, Bp + k0 + 4);
        }
        cp_commit();

        const float* a = As + (kc & 3) * GSTG;
        const float* b = Bs + (kc & 3) * GSTG;
#pragma unroll
        for (int ks = 0; ks < 16; ks += 8) {
            uint32_t af[2][4], bf[8][2];
#pragma unroll
            for (int mt = 0; mt < 2; mt++) {
                const int r = wm * 32 + mt * 16 + g;
                af[mt][0] = __float_as_uint(a[r * 20 + ks + tg]);
                af[mt][1] = __float_as_uint(a[(r + 8) * 20 + ks + tg]);
                af[mt][2] = __float_as_uint(a[r * 20 + ks + tg + 4]);
                af[mt][3] = __float_as_uint(a[(r + 8) * 20 + ks + tg + 4]);
            }
#pragma unroll
            for (int nt = 0; nt < 8; nt++) {
                const int n = wn * 64 + nt * 8 + g;
                bf[nt][0] = __float_as_uint(b[n * 20 + ks + tg]);
                bf[nt][1] = __float_as_uint(b[n * 20 + ks + tg + 4]);
            }
#pragma unroll
            for (int mt = 0; mt < 2; mt++)
#pragma unroll
                for (int nt = 0; nt < 8; nt++)
                    mma8(acc[mt][nt], af[mt], bf[nt]);
        }
    }

#pragma unroll
    for (int mt = 0; mt < 2; mt++) {
        const int r = row0 + wm * 32 + mt * 16 + g;
#pragma unroll
        for (int nt = 0; nt < 8; nt++) {
            const int cc = col0 + wn * 64 + nt * 8 + 2 * tg;
            float2 v0, v1;
            v0.x = acc[mt][nt][0] + bias[cc];
            v0.y = acc[mt][nt][1] + bias[cc + 1];
            v1.x = acc[mt][nt][2] + bias[cc];
            v1.y = acc[mt][nt][3] + bias[cc + 1];
            if (RND) {
                v0.x = f2tf(v0.x); v0.y = f2tf(v0.y);
                v1.x = f2tf(v1.x); v1.y = f2tf(v1.y);
            }
            *(float2*)(C + (size_t)r * N + cc)       = v0;
            *(float2*)(C + (size_t)(r + 8) * N + cc) = v1;
        }
    }
}

// ---------------- scores: 128x128 tiles, K split in 2 cp.async phases ----------
__global__ __launch_bounds__(256, 2) void scores_v5(
    const float* __restrict__ QKV, float* __restrict__ attn)
{
    const int kt = blockIdx.x, qt = blockIdx.y, z = blockIdx.z;
    if (kt > qt) return;
    const int b = z >> 4, h = z & 15;

    extern __shared__ float sm[];
    float* Qs = sm;               // [128][68]
    float* Ks = sm + 128 * 68;    // [128][68]

    const int t = threadIdx.x, lane = t & 31, w = t >> 5;
    const int g = lane >> 2, tg = lane & 3;
    const int wm = w & 3, wn = w >> 2;

    const int lrow = t >> 1, c0 = (t & 1) * 16;
    const float* Qp = QKV + ((size_t)(b * SS) + qt * 128 + lrow) * 3072 + h * 64;
    const float* Kp = QKV + ((size_t)(b * SS) + kt * 128 + lrow) * 3072 + DD + h * 64;
    float* Qsd = Qs + lrow * 68;
    float* Ksd = Ks + lrow * 68;

    // phase 0: k-cols [0,32)
#pragma unroll
    for (int j = 0; j < 4; j++) {
        cp16(Qsd + c0 + j * 4, Qp + c0 + j * 4);
        cp16(Ksd + c0 + j * 4, Kp + c0 + j * 4);
    }
    cp_commit();
    // phase 1: k-cols [32,64)
#pragma unroll
    for (int j = 0; j < 4; j++) {
        cp16(Qsd + 32 + c0 + j * 4, Qp + 32 + c0 + j * 4);
        cp16(Ksd + 32 + c0 + j * 4, Kp + 32 + c0 + j * 4);
    }
    cp_commit();

    float acc[2][8][4];
#pragma unroll
    for (int i = 0; i < 2; i++)
#pragma unroll
        for (int j = 0; j < 8; j++)
#pragma unroll
            for (int q = 0; q < 4; q++) acc[i][j][q] = 0.f;

    cp_wait<1>();
    __syncthreads();

#pragma unroll
    for (int half = 0; half < 2; half++) {
#pragma unroll
        for (int ks0 = 0; ks0 < 32; ks0 += 8) {
            const int ks = half * 32 + ks0;
            uint32_t af[2][4], bf[8][2];
#pragma unroll
            for (int mt = 0; mt < 2; mt++) {
                const int r = wm * 32 + mt * 16 + g;
                af[mt][0] = __float_as_uint(Qs[r * 68 + ks + tg]);
                af[mt][1] = __float_as_uint(Qs[(r + 8) * 68 + ks + tg]);
                af[mt][2] = __float_as_uint(Qs[r * 68 + ks + tg + 4]);
                af[mt][3] = __float_as_uint(Qs[(r + 8) * 68 + ks + tg + 4]);
            }
#pragma unroll
            for (int nt = 0; nt < 8; nt++) {
                const int n = wn * 64 + nt * 8 + g;
                bf[nt][0] = __float_as_uint(Ks[n * 68 + ks + tg]);
                bf[nt][1] = __float_as_uint(Ks[n * 68 + ks + tg + 4]);
            }
#pragma unroll
            for (int mt = 0; mt < 2; mt++)
#pragma unroll
                for (int nt = 0; nt < 8; nt++)
                    mma8(acc[mt][nt], af[mt], bf[nt]);
        }
        if (half == 0) {
            cp_wait<0>();
            __syncthreads();
        }
    }

#pragma unroll
    for (int mt = 0; mt < 2; mt++) {
        const int r = qt * 128 + wm * 32 + mt * 16 + g;
#pragma unroll
        for (int nt = 0; nt < 8; nt++) {
            const int cc = kt * 128 + wn * 64 + nt * 8 + 2 * tg;
            float2 v0, v1;
            v0.x = acc[mt][nt][0] * ATT_SCALE; v0.y = acc[mt][nt][1] * ATT_SCALE;
            v1.x = acc[mt][nt][2] * ATT_SCALE; v1.y = acc[mt][nt][3] * ATT_SCALE;
            *(float2*)(attn + ((size_t)z * SS + r) * SS + cc)       = v0;
            *(float2*)(attn + ((size_t)z * SS + r + 8) * SS + cc)   = v1;
        }
    }
}

// ---------------- row softmax with causal mask (float4, zero-fills masked) ----------
__global__ __launch_bounds__(256) void softmax_v5(float* __restrict__ attn)
{
    const size_t row = blockIdx.x;           // row = z*S + q
    const int q = (int)(row & (SS - 1));
    float4* p = (float4*)(attn + row * (size_t)SS);
    const int t = threadIdx.x;

    float4 va = p[t], vb = p[t + 256];
    const int ia = 4 * t, ib = 1024 + 4 * t;
    va.x = (ia     <= q) ? va.x : -1e30f;
    va.y = (ia + 1 <= q) ? va.y : -1e30f;
    va.z = (ia + 2 <= q) ? va.z : -1e30f;
    va.w = (ia + 3 <= q) ? va.w : -1e30f;
    vb.x = (ib     <= q) ? vb.x : -1e30f;
    vb.y = (ib + 1 <= q) ? vb.y : -1e30f;
    vb.z = (ib + 2 <= q) ? vb.z : -1e30f;
    vb.w = (ib + 3 <= q) ? vb.w : -1e30f;

    float m = fmaxf(fmaxf(fmaxf(va.x, va.y), fmaxf(va.z, va.w)),
                    fmaxf(fmaxf(vb.x, vb.y), fmaxf(vb.z, vb.w)));
#pragma unroll
    for (int o = 16; o > 0; o >>= 1) m = fmaxf(m, __shfl_xor_sync(0xffffffffu, m, o));
    __shared__ float redm[8];
    __shared__ float reds[8];
    if ((t & 31) == 0) redm[t >> 5] = m;
    __syncthreads();
    float bm = redm[0];
#pragma unroll
    for (int w = 1; w < 8; w++) bm = fmaxf(bm, redm[w]);

    va.x = (ia     <= q) ? __expf(va.x - bm) : 0.f;
    va.y = (ia + 1 <= q) ? __expf(va.y - bm) : 0.f;
    va.z = (ia + 2 <= q) ? __expf(va.z - bm) : 0.f;
    va.w = (ia + 3 <= q) ? __expf(va.w - bm) : 0.f;
    vb.x = (ib     <= q) ? __expf(vb.x - bm) : 0.f;
    vb.y = (ib + 1 <= q) ? __expf(vb.y - bm) : 0.f;
    vb.z = (ib + 2 <= q) ? __expf(vb.z - bm) : 0.f;
    vb.w = (ib + 3 <= q) ? __expf(vb.w - bm) : 0.f;

    float s = va.x + va.y + va.z + va.w + vb.x + vb.y + vb.z + vb.w;
#pragma unroll
    for (int o = 16; o > 0; o >>= 1) s += __shfl_xor_sync(0xffffffffu, s, o);
    if ((t & 31) == 0) reds[t >> 5] = s;
    __syncthreads();
    float tot = 0.f;
#pragma unroll
    for (int w = 0; w < 8; w++) tot += reds[w];
    const float inv = 1.0f / tot;

    va.x *= inv; va.y *= inv; va.z *= inv; va.w *= inv;
    vb.x *= inv; vb.y *= inv; vb.z *= inv; vb.w *= inv;
    p[t] = va;
    p[t + 256] = vb;
}

// ---------------- ctx = attn @ V, 128q x 64d tiles, 2-stage cp.async ----------
#define PSTG (128*68)
#define VSTG (64*72)
__global__ __launch_bounds__(256, 2) void ctx_v3(
    const float* __restrict__ attn, const float* __restrict__ QKV,
    float* __restrict__ Cout)
{
    extern __shared__ float sm[];
    float* Ps = sm;                 // [2][128][68]
    float* Vs = sm + 2 * PSTG;      // [2][64][72]

    const int qt = 15 - blockIdx.x;       // reversed: longest blocks first
    const int z = blockIdx.y;
    const int b = z >> 4, h = z & 15;
    const int t = threadIdx.x, lane = t & 31, w = t >> 5;
    const int g = lane >> 2, tg = lane & 3;
    const int wm = w & 3, wn = w >> 2;

    const int prow = t >> 1, pseg = (t & 1) * 32;
    const int vrow = t >> 2, vseg = (t & 3) * 16;
    const float* Pp = attn + ((size_t)z * SS + qt * 128 + prow) * SS + pseg;
    const float* Vp = QKV + ((size_t)(b * SS) + vrow) * 3072 + 2 * DD + h * 64 + vseg;
    float* Psd = Ps + prow * 68 + pseg;
    float* Vsd = Vs + vrow * 72 + vseg;

    const int cnt = 2 * qt + 2;

    float acc[2][4][4];
#pragma unroll
    for (int i = 0; i < 2; i++)
#pragma unroll
        for (int j = 0; j < 4; j++)
#pragma unroll
            for (int q = 0; q < 4; q++) acc[i][j][q] = 0.f;

    // prologue: stage 0 = kt 0
    {
#pragma unroll
        for (int j = 0; j < 8; j++) cp16(Psd + j * 4, Pp + j * 4);
#pragma unroll
        for (int j = 0; j < 4; j++) cp16(Vsd + j * 4, Vp + j * 4);
        cp_commit();
    }

    for (int kti = 0; kti < cnt; kti++) {
        if (kti + 1 < cnt) {
            const int st = (kti + 1) & 1;
#pragma unroll
            for (int j = 0; j < 8; j++)
                cp16(Psd + st * PSTG + j * 4, Pp + (kti + 1) * 64 + j * 4);
#pragma unroll
            for (int j = 0; j < 4; j++)
                cp16(Vsd + st * VSTG + j * 4, Vp + (size_t)(kti + 1) * 64 * 3072 + j * 4);
        }
        cp_commit();
        cp_wait<1>();
        __syncthreads();

        const float* pp = Ps + (kti & 1) * PSTG;
        const float* vv = Vs + (kti & 1) * VSTG;
#pragma unroll
        for (int ks = 0; ks < 64; ks += 8) {
            uint32_t af[2][4], bf[4][2];
#pragma unroll
            for (int mt = 0; mt < 2; mt++) {
                const int r = wm * 32 + mt * 16 + g;
                af[mt][0] = __float_as_uint(pp[r * 68 + ks + tg]);
                af[mt][1] = __float_as_uint(pp[(r + 8) * 68 + ks + tg]);
                af[mt][2] = __float_as_uint(pp[r * 68 + ks + tg + 4]);
                af[mt][3] = __float_as_uint(pp[(r + 8) * 68 + ks + tg + 4]);
            }
#pragma unroll
            for (int nt = 0; nt < 4; nt++) {
                const int n = wn * 32 + nt * 8 + g;
                bf[nt][0] = __float_as_uint(vv[(ks + tg) * 72 + n]);
                bf[nt][1] = __float_as_uint(vv[(ks + tg + 4) * 72 + n]);
            }
#pragma unroll
            for (int mt = 0; mt < 2; mt++)
#pragma unroll
                for (int nt = 0; nt < 4; nt++)
                    mma8(acc[mt][nt], af[mt], bf[nt]);
        }
        __syncthreads();
    }

#pragma unroll
    for (int mt = 0; mt < 2; mt++) {
        const int qrow = qt * 128 + wm * 32 + mt * 16 + g;
#pragma unroll
        for (int nt = 0; nt < 4; nt++) {
            const int cc = h * 64 + wn * 32 + nt * 8 + 2 * tg;
            float2 v0, v1;
            v0.x = f2tf(acc[mt][nt][0]); v0.y = f2tf(acc[mt][nt][1]);
            v1.x = f2tf(acc[mt][nt][2]); v1.y = f2tf(acc[mt][nt][3]);
            *(float2*)(Cout + ((size_t)(b * SS) + qrow) * DD + cc)     = v0;
            *(float2*)(Cout + ((size_t)(b * SS) + qrow + 8) * DD + cc) = v1;
        }
    }
}

// ---------------- launch ----------------
extern "C" void kernel_launch(void* const* d_in, const int* in_sizes, int n_in,
                              void* d_out, int out_size)
{
    const float* x  = (const float*)d_in[0];
    const float* Wq = (const float*)d_in[1];
    const float* bq = (const float*)d_in[2];
    const float* Wk = (const float*)d_in[3];
    const float* bk = (const float*)d_in[4];
    const float* Wv = (const float*)d_in[5];
    const float* bv = (const float*)d_in[6];
    const float* Wo = (const float*)d_in[7];
    const float* bo = (const float*)d_in[8];

    float* out  = (float*)d_out;
    float* attn = out + (size_t)NR * DD;   // tuple order: (out, attn)

    float *pW3, *pWo, *pb3, *pX, *pQKV, *pC;
    cudaGetSymbolAddress((void**)&pW3,  g_W3);
    cudaGetSymbolAddress((void**)&pWo,  g_Wo);
    cudaGetSymbolAddress((void**)&pb3,  g_b3);
    cudaGetSymbolAddress((void**)&pX,   g_X);
    cudaGetSymbolAddress((void**)&pQKV, g_QKV);
    cudaGetSymbolAddress((void**)&pC,   g_C);

    const int gemm_smem   = 4 * GSTG * 2 * 4;            // 81920
    const int scores_smem = 2 * 128 * 68 * 4;            // 69632
    const int ctx_smem    = (2 * PSTG + 2 * VSTG) * 4;   // 106496
    cudaFuncSetAttribute(gemm_v3<true>,  cudaFuncAttributeMaxDynamicSharedMemorySize, gemm_smem);
    cudaFuncSetAttribute(gemm_v3<false>, cudaFuncAttributeMaxDynamicSharedMemorySize, gemm_smem);
    cudaFuncSetAttribute(scores_v5,      cudaFuncAttributeMaxDynamicSharedMemorySize, scores_smem);
    cudaFuncSetAttribute(ctx_v3,         cudaFuncAttributeMaxDynamicSharedMemorySize, ctx_smem);

    // 1) prep: concat+round weights (float4), round x (float4)
    concat_kernel<<<(DD * DD / 4) / 256, 256>>>(
        (const float4*)Wq, (const float4*)Wk, (const float4*)Wv, (const float4*)Wo,
        bq, bk, bv);
    roundx_kernel<<<((size_t)NR * DD / 4) / 256, 256>>>((const float4*)x);

    // 2) fused QKV projection (stores tf32-rounded outputs)
    gemm_v3<true><<<dim3(3072 / 128, NR / 128), 256, gemm_smem>>>(pX, pW3, pb3, pQKV, NR, 3072, DD);

    // 3) raw causal scores into attn region (pipelined K-split)
    scores_v5<<<dim3(SS / 128, SS / 128, BB * HH), 256, scores_smem>>>(pQKV, attn);

    // 4) softmax per row (float4; also zero-fills masked region)
    softmax_v5<<<BB * HH * SS, 256>>>(attn);

    // 5) ctx = attn @ V (stores tf32-rounded ctx)
    ctx_v3<<<dim3(SS / 128, BB * HH), 256, ctx_smem>>>(attn, pQKV, pC);

    // 6) output projection (exact fp32 epilogue)
    gemm_v3<false><<<dim3(DD / 128, NR / 128), 256, gemm_smem>>>(pC, pWo, bo, out, NR, DD, DD);
}